// round 4
// baseline (speedup 1.0000x reference)
#include <cuda_runtime.h>
#include <math.h>

#define MAX_IN 64
#define D_MODEL 64
#define THREADS 256
#define ROWS_PER_GRAB 4

__device__ int g_ctr;

__device__ __forceinline__ float fast_tanh(float x) {
    float y;
    asm("tanh.approx.f32 %0, %1;" : "=f"(y) : "f"(x));
    return y;
}

__device__ __forceinline__ float gelu_tanh(float v) {
    const float c = 0.7978845608028654f;
    float u = c * (v + 0.044715f * v * v * v);
    return 0.5f * v * (1.0f + fast_tanh(u));
}

__global__ void k_reset() { g_ctr = 0; }

__global__ __launch_bounds__(THREADS, 5)
void fe_kernel(const float* __restrict__ seg,
               const float* __restrict__ W,
               const float* __restrict__ b,
               const int*   __restrict__ lengths,
               float* __restrict__ out,
               int n)
{
    const int lane  = threadIdx.x & 31;
    const int ihalf = lane >> 4;        // 0 or 1: which 4-group of i this lane covers
    const int chunk = lane & 15;        // d-chunk (float4 over D_MODEL)

    while (true) {
        int base;
        if (lane == 0) base = atomicAdd(&g_ctr, ROWS_PER_GRAB);
        base = __shfl_sync(0xffffffffu, base, 0);
        if (base >= n) break;

        int rend = min(base + ROWS_PER_GRAB, n);
        for (int row = base; row < rend; ++row) {
            const int len = __ldg(&lengths[row]);          // uniform across warp
            const int len4 = (len + 3) & ~3;
            const float4* Wr = reinterpret_cast<const float4*>(W)
                               + (size_t)row * 1024 + chunk;
            const float4* xr = reinterpret_cast<const float4*>(seg)
                               + (size_t)row * 16 + ihalf; // broadcast within half

            float4 acc = make_float4(0.f, 0.f, 0.f, 0.f);

            // Warp covers 8 i's per iteration: lanes 0-15 do i..i+3, lanes 16-31 do i+4..i+7.
            // Tail 4-group (when len4/4 is odd) handled by ihalf==0 lanes only.
            #pragma unroll 1
            for (int i = 0; i < len4; i += 8) {
                const int iv = i + 4 * ihalf;    // this lane's base i
                const bool act = iv < len4;      // tail: upper half may be idle
                float4 w0, w1, w2, w3, xv;
                if (act) {
                    w0 = Wr[(iv + 0) * 16];
                    w1 = Wr[(iv + 1) * 16];
                    w2 = Wr[(iv + 2) * 16];
                    w3 = Wr[(iv + 3) * 16];
                    xv = xr[i >> 2];
                    // mask x beyond true length (zero-pad)
                    if (iv + 0 >= len) xv.x = 0.f;
                    if (iv + 1 >= len) xv.y = 0.f;
                    if (iv + 2 >= len) xv.z = 0.f;
                    if (iv + 3 >= len) xv.w = 0.f;
                    acc.x += xv.x * w0.x + xv.y * w1.x + xv.z * w2.x + xv.w * w3.x;
                    acc.y += xv.x * w0.y + xv.y * w1.y + xv.z * w2.y + xv.w * w3.y;
                    acc.z += xv.x * w0.z + xv.y * w1.z + xv.z * w2.z + xv.w * w3.z;
                    acc.w += xv.x * w0.w + xv.y * w1.w + xv.z * w2.w + xv.w * w3.w;
                }
            }

            // Combine the two i-halves: shfl-xor 16
            acc.x += __shfl_xor_sync(0xffffffffu, acc.x, 16);
            acc.y += __shfl_xor_sync(0xffffffffu, acc.y, 16);
            acc.z += __shfl_xor_sync(0xffffffffu, acc.z, 16);
            acc.w += __shfl_xor_sync(0xffffffffu, acc.w, 16);

            if (ihalf == 0) {
                float4 bb = reinterpret_cast<const float4*>(b)[(size_t)row * 16 + chunk];
                float4 r4;
                r4.x = gelu_tanh(acc.x + bb.x);
                r4.y = gelu_tanh(acc.y + bb.y);
                r4.z = gelu_tanh(acc.z + bb.z);
                r4.w = gelu_tanh(acc.w + bb.w);
                reinterpret_cast<float4*>(out)[(size_t)row * 16 + chunk] = r4;
            }
        }
    }
}

extern "C" void kernel_launch(void* const* d_in, const int* in_sizes, int n_in,
                              void* d_out, int out_size) {
    const float* seg     = (const float*)d_in[0];
    const float* W       = (const float*)d_in[1];
    const float* b       = (const float*)d_in[2];
    const int*   lengths = (const int*)d_in[3];
    float* out = (float*)d_out;

    int n = in_sizes[3];

    k_reset<<<1, 1>>>();
    // Persistent-ish grid: 148 SMs * 5 blocks; work stealing drains the queue.
    fe_kernel<<<148 * 5, THREADS>>>(seg, W, b, lengths, out, n);
}